// round 1
// baseline (speedup 1.0000x reference)
#include <cuda_runtime.h>
#include <cstdint>

// ---------------- problem constants ----------------
constexpr int BATCH = 2, DEPTH = 32, HEIGHT = 64, WIDTH = 64, CH = 128;
constexpr int HEADS = 4, HD = 32, NTOK = 64;                 // window 4x4x4
constexpr int NWIN_PER_B = (DEPTH/4)*(HEIGHT/4)*(WIDTH/4);   // 2048
constexpr int NWIN = BATCH * NWIN_PER_B;                     // 4096
constexpr long long MROWS = (long long)NWIN * NTOK;          // 262144
constexpr int HID = 512;

// ---------------- scratch (static device globals; no allocation) ----------------
__device__ __align__(16) float g_xw  [MROWS * CH];     // LN1+shift+partition output
__device__ __align__(16) float g_q   [MROWS * CH];     // [win][head][n][hd]
__device__ __align__(16) float g_k   [MROWS * CH];
__device__ __align__(16) float g_v   [MROWS * CH];
__device__ __align__(16) float g_bias[HEADS * NTOK * NTOK];
__device__ __align__(16) float g_attn[MROWS * CH];     // attention output, window layout
__device__ __align__(16) float g_x1  [MROWS * CH];     // shortcut + attn (natural layout)
__device__ __align__(16) float g_xn2 [MROWS * CH];     // LN2 output
__device__ __align__(16) float g_hid [MROWS * HID];    // MLP hidden

// ---------------- LN1 + cyclic shift + window partition ----------------
// warp per token. shifted[ds] = xn[(ds+2) mod dim]
__global__ __launch_bounds__(256) void ln1_shift_kernel(
    const float* __restrict__ x, const float* __restrict__ sc, const float* __restrict__ bi)
{
    int warp = (blockIdx.x * 256 + threadIdx.x) >> 5;
    int lane = threadIdx.x & 31;
    int t = warp & 63, win = warp >> 6;
    int b = win >> 11, widx = win & 2047;
    int wd = widx >> 8, wh = (widx >> 4) & 15, ww = widx & 15;
    int td = t >> 4, th = (t >> 2) & 3, tw = t & 3;
    int d = (wd*4 + td + 2) & 31;
    int h = (wh*4 + th + 2) & 63;
    int w = (ww*4 + tw + 2) & 63;
    const float4* src = (const float4*)(x + ((size_t)(((b*32 + d)*64 + h)*64 + w)) * CH);
    float4 v = src[lane];
    float s  = v.x + v.y + v.z + v.w;
    float ss = v.x*v.x + v.y*v.y + v.z*v.z + v.w*v.w;
    #pragma unroll
    for (int o = 16; o; o >>= 1) {
        s  += __shfl_xor_sync(0xffffffffu, s,  o);
        ss += __shfl_xor_sync(0xffffffffu, ss, o);
    }
    float mean = s * (1.0f/128.0f);
    float var  = ss * (1.0f/128.0f) - mean*mean;
    float r = rsqrtf(var + 1e-6f);
    float4 g4 = ((const float4*)sc)[lane];
    float4 b4 = ((const float4*)bi)[lane];
    float4 o4;
    o4.x = (v.x - mean)*r*g4.x + b4.x;
    o4.y = (v.y - mean)*r*g4.y + b4.y;
    o4.z = (v.z - mean)*r*g4.z + b4.z;
    o4.w = (v.w - mean)*r*g4.w + b4.w;
    ((float4*)(g_xw + (size_t)warp * CH))[lane] = o4;
}

// ---------------- LN2 (plain, natural layout) ----------------
__global__ __launch_bounds__(256) void ln2_kernel(
    const float* __restrict__ sc, const float* __restrict__ bi)
{
    int warp = (blockIdx.x * 256 + threadIdx.x) >> 5;
    int lane = threadIdx.x & 31;
    float4 v = ((const float4*)(g_x1 + (size_t)warp * CH))[lane];
    float s  = v.x + v.y + v.z + v.w;
    float ss = v.x*v.x + v.y*v.y + v.z*v.z + v.w*v.w;
    #pragma unroll
    for (int o = 16; o; o >>= 1) {
        s  += __shfl_xor_sync(0xffffffffu, s,  o);
        ss += __shfl_xor_sync(0xffffffffu, ss, o);
    }
    float mean = s * (1.0f/128.0f);
    float var  = ss * (1.0f/128.0f) - mean*mean;
    float r = rsqrtf(var + 1e-6f);
    float4 g4 = ((const float4*)sc)[lane];
    float4 b4 = ((const float4*)bi)[lane];
    float4 o4;
    o4.x = (v.x - mean)*r*g4.x + b4.x;
    o4.y = (v.y - mean)*r*g4.y + b4.y;
    o4.z = (v.z - mean)*r*g4.z + b4.z;
    o4.w = (v.w - mean)*r*g4.w + b4.w;
    ((float4*)(g_xn2 + (size_t)warp * CH))[lane] = o4;
}

// ---------------- relative position bias precompute ----------------
// replicates np.meshgrid('xy'): c0 = th, c1 = td, c2 = tw
__global__ void bias_kernel(const float* __restrict__ table)
{
    int q = blockIdx.x;   // 0..63
    int k = threadIdx.x;  // 0..63
    int qd = q >> 4, qh = (q >> 2) & 3, qw = q & 3;
    int kd = k >> 4, kh = (k >> 2) & 3, kw = k & 3;
    int idx = (qh - kh + 3) * 49 + (qd - kd + 3) * 7 + (qw - kw + 3);
    #pragma unroll
    for (int h = 0; h < HEADS; h++)
        g_bias[h * 4096 + q * 64 + k] = table[idx * HEADS + h];
}

// ---------------- generic tiled GEMM: C(64x128 tile) = A[M,K] @ B[K,ldb] ----------------
// 256 threads, 4x8 register tile per thread. Epilogue functor does the store.
template <class Epi>
__global__ __launch_bounds__(256) void gemm_kernel(
    const float* __restrict__ A, const float* __restrict__ B,
    int K, int ldb, Epi epi)
{
    __shared__ float As[64][32];
    __shared__ float Bs[32][128];
    const int row0 = blockIdx.x * 64;
    const int col0 = blockIdx.y * 128;
    const int tid  = threadIdx.x;
    const int tm0 = (tid >> 4) << 2;   // 0..60
    const int tn0 = (tid & 15) << 3;   // 0..120

    float acc[4][8];
    #pragma unroll
    for (int i = 0; i < 4; i++)
        #pragma unroll
        for (int j = 0; j < 8; j++) acc[i][j] = 0.0f;

    for (int k0 = 0; k0 < K; k0 += 32) {
        // load A 64x32 (coalesced float4)
        #pragma unroll
        for (int i = 0; i < 2; i++) {
            int f = tid + i * 256;         // 512 float4 total
            int r = f >> 3, kq = f & 7;
            float4 v = *(const float4*)(A + (size_t)(row0 + r) * K + k0 + kq * 4);
            *(float4*)(&As[r][kq * 4]) = v;
        }
        // load B 32x128 (coalesced float4)
        #pragma unroll
        for (int i = 0; i < 4; i++) {
            int f = tid + i * 256;         // 1024 float4 total
            int r = f >> 5, c = (f & 31) << 2;
            float4 v = *(const float4*)(B + (size_t)(k0 + r) * ldb + col0 + c);
            *(float4*)(&Bs[r][c]) = v;
        }
        __syncthreads();
        #pragma unroll
        for (int k = 0; k < 32; k++) {
            float a0 = As[tm0    ][k];
            float a1 = As[tm0 + 1][k];
            float a2 = As[tm0 + 2][k];
            float a3 = As[tm0 + 3][k];
            float4 b0 = *(const float4*)(&Bs[k][tn0]);
            float4 b1 = *(const float4*)(&Bs[k][tn0 + 4]);
            float bb[8] = {b0.x, b0.y, b0.z, b0.w, b1.x, b1.y, b1.z, b1.w};
            #pragma unroll
            for (int j = 0; j < 8; j++) {
                acc[0][j] += a0 * bb[j];
                acc[1][j] += a1 * bb[j];
                acc[2][j] += a2 * bb[j];
                acc[3][j] += a3 * bb[j];
            }
        }
        __syncthreads();
    }
    #pragma unroll
    for (int i = 0; i < 4; i++)
        #pragma unroll
        for (int j = 0; j < 8; j++)
            epi(row0 + tm0 + i, col0 + tn0 + j, acc[i][j]);
}

// ---------------- epilogues ----------------
struct QkvEpi {
    __device__ void operator()(int m, int n, float v) const {
        int sel = n >> 7;          // 0=q 1=k 2=v
        int c = n & 127;
        int head = c >> 5, e = c & 31;
        int win = m >> 6, t = m & 63;
        size_t o = (((size_t)win * HEADS + head) * NTOK + t) * HD + e;
        if (sel == 0)      g_q[o] = v * 0.17677669529663687f;  // 1/sqrt(32)
        else if (sel == 1) g_k[o] = v;
        else               g_v[o] = v;
    }
};

struct ProjEpi {
    const float* x;   // original input (shortcut)
    const float* pb;  // proj bias
    __device__ void operator()(int m, int n, float v) const {
        int win = m >> 6, t = m & 63;
        int b = win >> 11, widx = win & 2047;
        int wd = widx >> 8, wh = (widx >> 4) & 15, ww = widx & 15;
        int td = t >> 4, th = (t >> 2) & 3, tw = t & 3;
        int d = (wd*4 + td + 2) & 31;
        int h = (wh*4 + th + 2) & 63;
        int w = (ww*4 + tw + 2) & 63;
        size_t o = (size_t)(((b*32 + d)*64 + h)*64 + w) * CH + n;
        g_x1[o] = v + pb[n] + x[o];
    }
};

struct Mlp1Epi {
    const float* b1;
    __device__ void operator()(int m, int n, float v) const {
        float u = v + b1[n];
        float u3 = u * u * u;
        float g = 0.5f * u * (1.0f + tanhf(0.7978845608028654f * (u + 0.044715f * u3)));
        g_hid[(size_t)m * HID + n] = g;
    }
};

struct Mlp2Epi {
    const float* b2;
    float* out;
    __device__ void operator()(int m, int n, float v) const {
        size_t o = (size_t)m * CH + n;
        out[o] = v + b2[n] + g_x1[o];
    }
};

// ---------------- attention: one block per (window, head), 64 threads ----------------
__global__ __launch_bounds__(64) void attn_kernel(const float* __restrict__ mask)
{
    const int blk  = blockIdx.x;        // win*4 + head
    const int win  = blk >> 2;
    const int head = blk & 3;
    const int t    = threadIdx.x;       // query row

    __shared__ float Ks[64][32];
    __shared__ float Vs[64][32];
    __shared__ float Ss[64][65];        // padded: bank-conflict-free per-row access

    const float4* kb = (const float4*)(g_k + (size_t)blk * (NTOK * HD));
    const float4* vb = (const float4*)(g_v + (size_t)blk * (NTOK * HD));
    #pragma unroll
    for (int i = 0; i < 8; i++) {
        int f = t + i * 64;             // 512 float4 per tile
        ((float4*)Ks)[f] = kb[f];
        ((float4*)Vs)[f] = vb[f];
    }
    __syncthreads();

    float qv[32];
    const float4* qr = (const float4*)(g_q + (size_t)blk * (NTOK * HD) + t * HD);
    #pragma unroll
    for (int i = 0; i < 8; i++) {
        float4 v = qr[i];
        qv[i*4+0] = v.x; qv[i*4+1] = v.y; qv[i*4+2] = v.z; qv[i*4+3] = v.w;
    }

    const float* mrow = mask + (size_t)(win & 2047) * 4096 + t * 64;
    const float* brow = g_bias + head * 4096 + t * 64;

    // pass 1: scores
    for (int j = 0; j < 64; j++) {
        const float4* kr = (const float4*)(&Ks[j][0]);
        float acc = 0.0f;
        #pragma unroll
        for (int i = 0; i < 8; i++) {
            float4 kv = kr[i];
            acc += qv[i*4+0]*kv.x + qv[i*4+1]*kv.y + qv[i*4+2]*kv.z + qv[i*4+3]*kv.w;
        }
        Ss[t][j] = acc + brow[j] + mrow[j];
    }

    // pass 2: softmax over own row
    float mx = -1e30f;
    for (int j = 0; j < 64; j++) mx = fmaxf(mx, Ss[t][j]);
    float sum = 0.0f;
    for (int j = 0; j < 64; j++) {
        float e = expf(Ss[t][j] - mx);
        Ss[t][j] = e;
        sum += e;
    }
    float inv = 1.0f / sum;

    // pass 3: P @ V
    float o[32];
    #pragma unroll
    for (int e = 0; e < 32; e++) o[e] = 0.0f;
    for (int j = 0; j < 64; j++) {
        float p = Ss[t][j] * inv;
        const float4* vr = (const float4*)(&Vs[j][0]);
        #pragma unroll
        for (int i = 0; i < 8; i++) {
            float4 vv = vr[i];
            o[i*4+0] += p * vv.x;
            o[i*4+1] += p * vv.y;
            o[i*4+2] += p * vv.z;
            o[i*4+3] += p * vv.w;
        }
    }
    float4* op = (float4*)(g_attn + ((size_t)win * NTOK + t) * CH + head * HD);
    #pragma unroll
    for (int i = 0; i < 8; i++) {
        float4 v;
        v.x = o[i*4+0]; v.y = o[i*4+1]; v.z = o[i*4+2]; v.w = o[i*4+3];
        op[i] = v;
    }
}

// ---------------- launcher ----------------
extern "C" void kernel_launch(void* const* d_in, const int* in_sizes, int n_in,
                              void* d_out, int out_size)
{
    const float* x       = (const float*)d_in[0];
    const float* mask    = (const float*)d_in[1];
    const float* n1s     = (const float*)d_in[2];
    const float* n1b     = (const float*)d_in[3];
    const float* qkv_w   = (const float*)d_in[4];
    const float* table   = (const float*)d_in[5];
    const float* proj_w  = (const float*)d_in[6];
    const float* proj_b  = (const float*)d_in[7];
    const float* n2s     = (const float*)d_in[8];
    const float* n2b     = (const float*)d_in[9];
    const float* mlp_w1  = (const float*)d_in[10];
    const float* mlp_b1  = (const float*)d_in[11];
    const float* mlp_w2  = (const float*)d_in[12];
    const float* mlp_b2  = (const float*)d_in[13];
    float* out = (float*)d_out;

    float *p_xw, *p_attn, *p_xn2, *p_hid;
    cudaGetSymbolAddress((void**)&p_xw,   g_xw);
    cudaGetSymbolAddress((void**)&p_attn, g_attn);
    cudaGetSymbolAddress((void**)&p_xn2,  g_xn2);
    cudaGetSymbolAddress((void**)&p_hid,  g_hid);

    const int ROWBLK = (int)(MROWS / 64);   // 4096

    // 1. LN1 + shift + window partition
    ln1_shift_kernel<<<(int)(MROWS / 8), 256>>>(x, n1s, n1b);
    // 2. relative position bias
    bias_kernel<<<64, 64>>>(table);
    // 3. QKV projection (q pre-scaled)
    gemm_kernel<<<dim3(ROWBLK, 3), 256>>>(p_xw, qkv_w, 128, 384, QkvEpi{});
    // 4. windowed attention
    attn_kernel<<<NWIN * HEADS, 64>>>(mask);
    // 5. output projection + window reverse + roll + residual
    gemm_kernel<<<dim3(ROWBLK, 1), 256>>>(p_attn, proj_w, 128, 128, ProjEpi{x, proj_b});
    // 6. LN2
    ln2_kernel<<<(int)(MROWS / 8), 256>>>(n2s, n2b);
    // 7. MLP up + GELU
    gemm_kernel<<<dim3(ROWBLK, 4), 256>>>(p_xn2, mlp_w1, 128, HID, Mlp1Epi{mlp_b1});
    // 8. MLP down + residual -> out
    gemm_kernel<<<dim3(ROWBLK, 1), 256>>>(p_hid, mlp_w2, HID, 128, Mlp2Epi{mlp_b2, out});
}

// round 3
// speedup vs baseline: 2.1570x; 2.1570x over previous
#include <cuda_runtime.h>
#include <cstdint>

// ---------------- problem constants ----------------
constexpr int CH = 128, HEADS = 4, HD = 32, NTOK = 64;
constexpr int NWIN = 4096;
constexpr long long MROWS = 262144;   // 4096 windows * 64 tokens
constexpr int HID = 512;

// ---------------- scratch (static device globals) ----------------
__device__ __align__(16) float g_xw  [MROWS * CH];
__device__ __align__(16) float g_q   [MROWS * CH];
__device__ __align__(16) float g_k   [MROWS * CH];
__device__ __align__(16) float g_v   [MROWS * CH];
__device__ __align__(16) float g_bias[HEADS * NTOK * NTOK];
__device__ __align__(16) float g_attn[MROWS * CH];
__device__ __align__(16) float g_x1  [MROWS * CH];
__device__ __align__(16) float g_xn2 [MROWS * CH];
__device__ __align__(16) float g_hid [MROWS * HID];
// transposed weights [N, K]
__device__ __align__(16) float g_wqkv_t[384 * 128];
__device__ __align__(16) float g_wproj_t[128 * 128];
__device__ __align__(16) float g_w1_t  [512 * 128];
__device__ __align__(16) float g_w2_t  [128 * 512];

__device__ __forceinline__ uint32_t f2tf32(float f) {
    uint32_t u;
    asm("cvt.rna.tf32.f32 %0, %1;" : "=r"(u) : "f"(f));
    return u;
}
__device__ __forceinline__ float4 cvt4(float4 v) {
    float4 o;
    o.x = __uint_as_float(f2tf32(v.x));
    o.y = __uint_as_float(f2tf32(v.y));
    o.z = __uint_as_float(f2tf32(v.z));
    o.w = __uint_as_float(f2tf32(v.w));
    return o;
}

// ---------------- LN1 + cyclic shift + window partition ----------------
__global__ __launch_bounds__(256) void ln1_shift_kernel(
    const float* __restrict__ x, const float* __restrict__ sc, const float* __restrict__ bi)
{
    int warp = (blockIdx.x * 256 + threadIdx.x) >> 5;
    int lane = threadIdx.x & 31;
    int t = warp & 63, win = warp >> 6;
    int b = win >> 11, widx = win & 2047;
    int wd = widx >> 8, wh = (widx >> 4) & 15, ww = widx & 15;
    int td = t >> 4, th = (t >> 2) & 3, tw = t & 3;
    int d = (wd*4 + td + 2) & 31;
    int h = (wh*4 + th + 2) & 63;
    int w = (ww*4 + tw + 2) & 63;
    const float4* src = (const float4*)(x + ((size_t)(((b*32 + d)*64 + h)*64 + w)) * CH);
    float4 v = src[lane];
    float s  = v.x + v.y + v.z + v.w;
    float ss = v.x*v.x + v.y*v.y + v.z*v.z + v.w*v.w;
    #pragma unroll
    for (int o = 16; o; o >>= 1) {
        s  += __shfl_xor_sync(0xffffffffu, s,  o);
        ss += __shfl_xor_sync(0xffffffffu, ss, o);
    }
    float mean = s * (1.0f/128.0f);
    float var  = ss * (1.0f/128.0f) - mean*mean;
    float r = rsqrtf(var + 1e-6f);
    float4 g4 = ((const float4*)sc)[lane];
    float4 b4 = ((const float4*)bi)[lane];
    float4 o4;
    o4.x = (v.x - mean)*r*g4.x + b4.x;
    o4.y = (v.y - mean)*r*g4.y + b4.y;
    o4.z = (v.z - mean)*r*g4.z + b4.z;
    o4.w = (v.w - mean)*r*g4.w + b4.w;
    ((float4*)(g_xw + (size_t)warp * CH))[lane] = o4;
}

// ---------------- LN2 ----------------
__global__ __launch_bounds__(256) void ln2_kernel(
    const float* __restrict__ sc, const float* __restrict__ bi)
{
    int warp = (blockIdx.x * 256 + threadIdx.x) >> 5;
    int lane = threadIdx.x & 31;
    float4 v = ((const float4*)(g_x1 + (size_t)warp * CH))[lane];
    float s  = v.x + v.y + v.z + v.w;
    float ss = v.x*v.x + v.y*v.y + v.z*v.z + v.w*v.w;
    #pragma unroll
    for (int o = 16; o; o >>= 1) {
        s  += __shfl_xor_sync(0xffffffffu, s,  o);
        ss += __shfl_xor_sync(0xffffffffu, ss, o);
    }
    float mean = s * (1.0f/128.0f);
    float var  = ss * (1.0f/128.0f) - mean*mean;
    float r = rsqrtf(var + 1e-6f);
    float4 g4 = ((const float4*)sc)[lane];
    float4 b4 = ((const float4*)bi)[lane];
    float4 o4;
    o4.x = (v.x - mean)*r*g4.x + b4.x;
    o4.y = (v.y - mean)*r*g4.y + b4.y;
    o4.z = (v.z - mean)*r*g4.z + b4.z;
    o4.w = (v.w - mean)*r*g4.w + b4.w;
    ((float4*)(g_xn2 + (size_t)warp * CH))[lane] = o4;
}

// ---------------- relative position bias ----------------
__global__ void bias_kernel(const float* __restrict__ table)
{
    int q = blockIdx.x, k = threadIdx.x;
    int qd = q >> 4, qh = (q >> 2) & 3, qw = q & 3;
    int kd = k >> 4, kh = (k >> 2) & 3, kw = k & 3;
    int idx = (qh - kh + 3) * 49 + (qd - kd + 3) * 7 + (qw - kw + 3);
    #pragma unroll
    for (int h = 0; h < HEADS; h++)
        g_bias[h * 4096 + q * 64 + k] = table[idx * HEADS + h];
}

// ---------------- weight transpose: dst[N,K] = src[K,N] ----------------
__global__ void transpose_kernel(const float* __restrict__ src, float* __restrict__ dst, int K, int N)
{
    __shared__ float tile[32][33];
    int n0 = blockIdx.x * 32, k0 = blockIdx.y * 32;
    int tx = threadIdx.x, ty = threadIdx.y;
    tile[ty][tx] = src[(size_t)(k0 + ty) * N + n0 + tx];
    __syncthreads();
    dst[(size_t)(n0 + ty) * K + k0 + tx] = tile[tx][ty];
}

// ---------------- epilogues ----------------
struct QkvEpi {
    __device__ void operator()(int m, int n, float v) const {
        int sel = n >> 7, c = n & 127;
        int head = c >> 5, e = c & 31;
        int win = m >> 6, t = m & 63;
        size_t o = (((size_t)win * HEADS + head) * NTOK + t) * HD + e;
        if (sel == 0)      g_q[o] = v * 0.17677669529663687f;
        else if (sel == 1) g_k[o] = v;
        else               g_v[o] = v;
    }
};
struct ProjEpi {
    const float* x; const float* pb;
    __device__ void operator()(int m, int n, float v) const {
        int win = m >> 6, t = m & 63;
        int b = win >> 11, widx = win & 2047;
        int wd = widx >> 8, wh = (widx >> 4) & 15, ww = widx & 15;
        int td = t >> 4, th = (t >> 2) & 3, tw = t & 3;
        int d = (wd*4 + td + 2) & 31;
        int h = (wh*4 + th + 2) & 63;
        int w = (ww*4 + tw + 2) & 63;
        size_t o = (size_t)(((b*32 + d)*64 + h)*64 + w) * CH + n;
        g_x1[o] = v + pb[n] + x[o];
    }
};
struct Mlp1Epi {
    const float* b1;
    __device__ void operator()(int m, int n, float v) const {
        float u = v + b1[n];
        float z2 = 1.5957691216057308f * (u + 0.044715f * u * u * u);
        float sig = 1.0f / (1.0f + __expf(-z2));
        g_hid[(size_t)m * HID + n] = u * sig;
    }
};
struct Mlp2Epi {
    const float* b2; float* out;
    __device__ void operator()(int m, int n, float v) const {
        size_t o = (size_t)m * CH + n;
        out[o] = v + b2[n] + g_x1[o];
    }
};

// ---------------- tf32 mma.sync GEMM ----------------
// C tile [128 x 128] = A[row0:row0+128, :KTOT] @ BT[col0:col0+128, :KTOT]^T
// 256 threads, 8 warps (4 M x 2 N), warp tile 32x64, BK=32, double-buffered smem.
// smem per buffer: As 128x36 + Bs 128x36 floats; stage reuses buffers for epilogue.
template<int KTOT, class Epi>
__global__ __launch_bounds__(256, 2) void gemm_mma(
    const float* __restrict__ A, const float* __restrict__ BT, Epi epi)
{
    extern __shared__ float sm[];   // 18432 floats = 73728 B
    const int tid = threadIdx.x;
    const int wid = tid >> 5, lane = tid & 31;
    const int row0 = blockIdx.x * 128, col0 = blockIdx.y * 128;
    const int wm0 = (wid >> 1) * 32, wn0 = (wid & 1) * 64;
    const int g = lane >> 2, tg = lane & 3;

    float acc[2][8][4];
    #pragma unroll
    for (int mt = 0; mt < 2; mt++)
        #pragma unroll
        for (int nt = 0; nt < 8; nt++)
            #pragma unroll
            for (int c = 0; c < 4; c++) acc[mt][nt][c] = 0.0f;

    float4 ra[4], rb[4];
    auto loadG = [&](int kc) {
        const float* pA = A + (size_t)row0 * KTOT + kc * 32;
        const float* pB = BT + (size_t)col0 * KTOT + kc * 32;
        #pragma unroll
        for (int i = 0; i < 4; i++) {
            int idx = tid + i * 256;
            int r = idx >> 3, c = (idx & 7) * 4;
            ra[i] = *(const float4*)(pA + (size_t)r * KTOT + c);
            rb[i] = *(const float4*)(pB + (size_t)r * KTOT + c);
        }
    };
    auto storeS = [&](int buf) {
        float* As_ = sm + buf * 9216;
        float* Bs_ = As_ + 4608;
        #pragma unroll
        for (int i = 0; i < 4; i++) {
            int idx = tid + i * 256;
            int r = idx >> 3, c = (idx & 7) * 4;
            *(float4*)(As_ + r * 36 + c) = cvt4(ra[i]);
            *(float4*)(Bs_ + r * 36 + c) = cvt4(rb[i]);
        }
    };
    auto compute = [&](int buf) {
        const float* As_ = sm + buf * 9216;
        const float* Bs_ = As_ + 4608;
        #pragma unroll
        for (int ks = 0; ks < 4; ks++) {
            const int kk = ks * 8;
            uint32_t a[2][4], b[8][2];
            #pragma unroll
            for (int mt = 0; mt < 2; mt++) {
                int r = wm0 + mt * 16;
                a[mt][0] = __float_as_uint(As_[(r + g    ) * 36 + kk + tg    ]);
                a[mt][1] = __float_as_uint(As_[(r + g + 8) * 36 + kk + tg    ]);
                a[mt][2] = __float_as_uint(As_[(r + g    ) * 36 + kk + tg + 4]);
                a[mt][3] = __float_as_uint(As_[(r + g + 8) * 36 + kk + tg + 4]);
            }
            #pragma unroll
            for (int nt = 0; nt < 8; nt++) {
                int n = wn0 + nt * 8 + g;
                b[nt][0] = __float_as_uint(Bs_[n * 36 + kk + tg    ]);
                b[nt][1] = __float_as_uint(Bs_[n * 36 + kk + tg + 4]);
            }
            #pragma unroll
            for (int mt = 0; mt < 2; mt++)
                #pragma unroll
                for (int nt = 0; nt < 8; nt++)
                    asm volatile(
                        "mma.sync.aligned.m16n8k8.row.col.f32.tf32.tf32.f32 "
                        "{%0,%1,%2,%3}, {%4,%5,%6,%7}, {%8,%9}, {%0,%1,%2,%3};"
                        : "+f"(acc[mt][nt][0]), "+f"(acc[mt][nt][1]),
                          "+f"(acc[mt][nt][2]), "+f"(acc[mt][nt][3])
                        : "r"(a[mt][0]), "r"(a[mt][1]), "r"(a[mt][2]), "r"(a[mt][3]),
                          "r"(b[nt][0]), "r"(b[nt][1]));
        }
    };

    constexpr int NKC = KTOT / 32;
    loadG(0);
    storeS(0);
    __syncthreads();
    #pragma unroll
    for (int kc = 0; kc < NKC; kc++) {
        if (kc + 1 < NKC) loadG(kc + 1);
        compute(kc & 1);
        __syncthreads();
        if (kc + 1 < NKC) {
            storeS((kc + 1) & 1);
            __syncthreads();
        }
    }

    // ---- epilogue: stage to smem, then coalesced reads -> epi ----
    float* st = sm;   // 128 x 132 floats
    #pragma unroll
    for (int mt = 0; mt < 2; mt++)
        #pragma unroll
        for (int nt = 0; nt < 8; nt++) {
            int r = wm0 + mt * 16;
            int c = wn0 + nt * 8 + tg * 2;
            *(float2*)(st + (r + g    ) * 132 + c) = make_float2(acc[mt][nt][0], acc[mt][nt][1]);
            *(float2*)(st + (r + g + 8) * 132 + c) = make_float2(acc[mt][nt][2], acc[mt][nt][3]);
        }
    __syncthreads();
    #pragma unroll
    for (int i = 0; i < 64; i++) {
        int idx = tid + i * 256;
        int m = idx >> 7, n = idx & 127;
        epi(row0 + m, col0 + n, st[m * 132 + n]);
    }
}

// ---------------- attention: one block per (window, head), 64 threads ----------------
// scores kept in registers; softmax without max-subtraction (scores are small; mask=-100 underflows safely)
__global__ __launch_bounds__(64) void attn_kernel(const float* __restrict__ mask)
{
    const int blk  = blockIdx.x;
    const int win  = blk >> 2;
    const int head = blk & 3;
    const int t    = threadIdx.x;

    __shared__ float Ks[64][32];
    __shared__ float Vs[64][32];

    const float4* kb = (const float4*)(g_k + (size_t)blk * (NTOK * HD));
    const float4* vb = (const float4*)(g_v + (size_t)blk * (NTOK * HD));
    #pragma unroll
    for (int i = 0; i < 8; i++) {
        int f = t + i * 64;
        ((float4*)Ks)[f] = kb[f];
        ((float4*)Vs)[f] = vb[f];
    }
    __syncthreads();

    float qv[32];
    const float4* qr = (const float4*)(g_q + (size_t)blk * (NTOK * HD) + t * HD);
    #pragma unroll
    for (int i = 0; i < 8; i++) {
        float4 v = qr[i];
        qv[i*4+0] = v.x; qv[i*4+1] = v.y; qv[i*4+2] = v.z; qv[i*4+3] = v.w;
    }

    const float* mrow = mask + (size_t)(win & 2047) * 4096 + t * 64;
    const float* brow = g_bias + head * 4096 + t * 64;

    float sc[64];
    float sum = 0.0f;
    #pragma unroll
    for (int j = 0; j < 64; j++) {
        const float4* kr = (const float4*)(&Ks[j][0]);
        float acc = 0.0f;
        #pragma unroll
        for (int i = 0; i < 8; i++) {
            float4 kv = kr[i];
            acc += qv[i*4+0]*kv.x + qv[i*4+1]*kv.y + qv[i*4+2]*kv.z + qv[i*4+3]*kv.w;
        }
        float e = __expf(acc + brow[j] + mrow[j]);
        sc[j] = e;
        sum += e;
    }
    float inv = 1.0f / sum;

    float o[32];
    #pragma unroll
    for (int e = 0; e < 32; e++) o[e] = 0.0f;
    #pragma unroll
    for (int j = 0; j < 64; j++) {
        float p = sc[j] * inv;
        const float4* vr = (const float4*)(&Vs[j][0]);
        #pragma unroll
        for (int i = 0; i < 8; i++) {
            float4 vv = vr[i];
            o[i*4+0] += p * vv.x;
            o[i*4+1] += p * vv.y;
            o[i*4+2] += p * vv.z;
            o[i*4+3] += p * vv.w;
        }
    }
    float4* op = (float4*)(g_attn + ((size_t)win * NTOK + t) * CH + head * HD);
    #pragma unroll
    for (int i = 0; i < 8; i++)
        op[i] = make_float4(o[i*4+0], o[i*4+1], o[i*4+2], o[i*4+3]);
}

// ---------------- launcher ----------------
extern "C" void kernel_launch(void* const* d_in, const int* in_sizes, int n_in,
                              void* d_out, int out_size)
{
    const float* x       = (const float*)d_in[0];
    const float* mask    = (const float*)d_in[1];
    const float* n1s     = (const float*)d_in[2];
    const float* n1b     = (const float*)d_in[3];
    const float* qkv_w   = (const float*)d_in[4];
    const float* table   = (const float*)d_in[5];
    const float* proj_w  = (const float*)d_in[6];
    const float* proj_b  = (const float*)d_in[7];
    const float* n2s     = (const float*)d_in[8];
    const float* n2b     = (const float*)d_in[9];
    const float* mlp_w1  = (const float*)d_in[10];
    const float* mlp_b1  = (const float*)d_in[11];
    const float* mlp_w2  = (const float*)d_in[12];
    const float* mlp_b2  = (const float*)d_in[13];
    float* out = (float*)d_out;

    float *p_xw, *p_xn2, *p_hid, *p_attn;
    float *p_wqkv_t, *p_wproj_t, *p_w1_t, *p_w2_t;
    cudaGetSymbolAddress((void**)&p_xw,     g_xw);
    cudaGetSymbolAddress((void**)&p_xn2,    g_xn2);
    cudaGetSymbolAddress((void**)&p_hid,    g_hid);
    cudaGetSymbolAddress((void**)&p_attn,   g_attn);
    cudaGetSymbolAddress((void**)&p_wqkv_t, g_wqkv_t);
    cudaGetSymbolAddress((void**)&p_wproj_t,g_wproj_t);
    cudaGetSymbolAddress((void**)&p_w1_t,   g_w1_t);
    cudaGetSymbolAddress((void**)&p_w2_t,   g_w2_t);

    const size_t DSM = 73728;  // 2 x (128x36 A + 128x36 B) floats
    cudaFuncSetAttribute(gemm_mma<128, QkvEpi>,  cudaFuncAttributeMaxDynamicSharedMemorySize, (int)DSM);
    cudaFuncSetAttribute(gemm_mma<128, ProjEpi>, cudaFuncAttributeMaxDynamicSharedMemorySize, (int)DSM);
    cudaFuncSetAttribute(gemm_mma<128, Mlp1Epi>, cudaFuncAttributeMaxDynamicSharedMemorySize, (int)DSM);
    cudaFuncSetAttribute(gemm_mma<512, Mlp2Epi>, cudaFuncAttributeMaxDynamicSharedMemorySize, (int)DSM);

    const int ROWBLK = (int)(MROWS / 128);  // 2048

    // weight transposes (small, L2-resident)
    transpose_kernel<<<dim3(12, 4),  dim3(32, 32)>>>(qkv_w,  p_wqkv_t, 128, 384);
    transpose_kernel<<<dim3(4, 4),   dim3(32, 32)>>>(proj_w, p_wproj_t, 128, 128);
    transpose_kernel<<<dim3(16, 4),  dim3(32, 32)>>>(mlp_w1, p_w1_t,   128, 512);
    transpose_kernel<<<dim3(4, 16),  dim3(32, 32)>>>(mlp_w2, p_w2_t,   512, 128);

    // 1. LN1 + shift + window partition
    ln1_shift_kernel<<<(int)(MROWS / 8), 256>>>(x, n1s, n1b);
    // 2. relative position bias
    bias_kernel<<<64, 64>>>(table);
    // 3. QKV projection (q pre-scaled)
    gemm_mma<128, QkvEpi><<<dim3(ROWBLK, 3), 256, DSM>>>(p_xw, p_wqkv_t, QkvEpi{});
    // 4. windowed attention
    attn_kernel<<<NWIN * HEADS, 64>>>(mask);
    // 5. output projection + window reverse + roll + residual
    gemm_mma<128, ProjEpi><<<dim3(ROWBLK, 1), 256, DSM>>>(p_attn, p_wproj_t, ProjEpi{x, proj_b});
    // 6. LN2
    ln2_kernel<<<(int)(MROWS / 8), 256>>>(n2s, n2b);
    // 7. MLP up + GELU
    gemm_mma<128, Mlp1Epi><<<dim3(ROWBLK, 4), 256, DSM>>>(p_xn2, p_w1_t, Mlp1Epi{mlp_b1});
    // 8. MLP down + residual -> out
    gemm_mma<512, Mlp2Epi><<<dim3(ROWBLK, 1), 256, DSM>>>(p_hid, p_w2_t, Mlp2Epi{mlp_b2, out});
}

// round 4
// speedup vs baseline: 2.7650x; 1.2818x over previous
#include <cuda_runtime.h>
#include <cstdint>

// ---------------- problem constants ----------------
constexpr int CH = 128, HEADS = 4, HD = 32, NTOK = 64;
constexpr int NWIN = 4096;
constexpr long long MROWS = 262144;   // 4096 windows * 64 tokens
constexpr int HID = 512;

// ---------------- scratch (static device globals) ----------------
__device__ __align__(16) float g_xw  [MROWS * CH];
__device__ __align__(16) float g_q   [MROWS * CH];
__device__ __align__(16) float g_k   [MROWS * CH];
__device__ __align__(16) float g_v   [MROWS * CH];
__device__ __align__(16) float g_bias[HEADS * NTOK * NTOK];
__device__ __align__(16) float g_attn[MROWS * CH];
__device__ __align__(16) float g_x1  [MROWS * CH];
__device__ __align__(16) float g_xn2 [MROWS * CH];
__device__ __align__(16) float g_hid [MROWS * HID];
// transposed weights [N, K]
__device__ __align__(16) float g_wqkv_t[384 * 128];
__device__ __align__(16) float g_wproj_t[128 * 128];
__device__ __align__(16) float g_w1_t  [512 * 128];
__device__ __align__(16) float g_w2_t  [128 * 512];

__device__ __forceinline__ uint32_t f2tf32(float f) {
    uint32_t u;
    asm("cvt.rna.tf32.f32 %0, %1;" : "=r"(u) : "f"(f));
    return u;
}
__device__ __forceinline__ float4 cvt4(float4 v) {
    float4 o;
    o.x = __uint_as_float(f2tf32(v.x));
    o.y = __uint_as_float(f2tf32(v.y));
    o.z = __uint_as_float(f2tf32(v.z));
    o.w = __uint_as_float(f2tf32(v.w));
    return o;
}
#define MMA_TF32(acc, a, b) \
    asm volatile("mma.sync.aligned.m16n8k8.row.col.f32.tf32.tf32.f32 " \
        "{%0,%1,%2,%3}, {%4,%5,%6,%7}, {%8,%9}, {%0,%1,%2,%3};" \
        : "+f"((acc)[0]), "+f"((acc)[1]), "+f"((acc)[2]), "+f"((acc)[3]) \
        : "r"((a)[0]), "r"((a)[1]), "r"((a)[2]), "r"((a)[3]), "r"((b)[0]), "r"((b)[1]))

// ---------------- LN1 + cyclic shift + window partition ----------------
__global__ __launch_bounds__(256) void ln1_shift_kernel(
    const float* __restrict__ x, const float* __restrict__ sc, const float* __restrict__ bi)
{
    int warp = (blockIdx.x * 256 + threadIdx.x) >> 5;
    int lane = threadIdx.x & 31;
    int t = warp & 63, win = warp >> 6;
    int b = win >> 11, widx = win & 2047;
    int wd = widx >> 8, wh = (widx >> 4) & 15, ww = widx & 15;
    int td = t >> 4, th = (t >> 2) & 3, tw = t & 3;
    int d = (wd*4 + td + 2) & 31;
    int h = (wh*4 + th + 2) & 63;
    int w = (ww*4 + tw + 2) & 63;
    const float4* src = (const float4*)(x + ((size_t)(((b*32 + d)*64 + h)*64 + w)) * CH);
    float4 v = src[lane];
    float s  = v.x + v.y + v.z + v.w;
    float ss = v.x*v.x + v.y*v.y + v.z*v.z + v.w*v.w;
    #pragma unroll
    for (int o = 16; o; o >>= 1) {
        s  += __shfl_xor_sync(0xffffffffu, s,  o);
        ss += __shfl_xor_sync(0xffffffffu, ss, o);
    }
    float mean = s * (1.0f/128.0f);
    float var  = ss * (1.0f/128.0f) - mean*mean;
    float r = rsqrtf(var + 1e-6f);
    float4 g4 = ((const float4*)sc)[lane];
    float4 b4 = ((const float4*)bi)[lane];
    float4 o4;
    o4.x = (v.x - mean)*r*g4.x + b4.x;
    o4.y = (v.y - mean)*r*g4.y + b4.y;
    o4.z = (v.z - mean)*r*g4.z + b4.z;
    o4.w = (v.w - mean)*r*g4.w + b4.w;
    ((float4*)(g_xw + (size_t)warp * CH))[lane] = o4;
}

// ---------------- LN2 ----------------
__global__ __launch_bounds__(256) void ln2_kernel(
    const float* __restrict__ sc, const float* __restrict__ bi)
{
    int warp = (blockIdx.x * 256 + threadIdx.x) >> 5;
    int lane = threadIdx.x & 31;
    float4 v = ((const float4*)(g_x1 + (size_t)warp * CH))[lane];
    float s  = v.x + v.y + v.z + v.w;
    float ss = v.x*v.x + v.y*v.y + v.z*v.z + v.w*v.w;
    #pragma unroll
    for (int o = 16; o; o >>= 1) {
        s  += __shfl_xor_sync(0xffffffffu, s,  o);
        ss += __shfl_xor_sync(0xffffffffu, ss, o);
    }
    float mean = s * (1.0f/128.0f);
    float var  = ss * (1.0f/128.0f) - mean*mean;
    float r = rsqrtf(var + 1e-6f);
    float4 g4 = ((const float4*)sc)[lane];
    float4 b4 = ((const float4*)bi)[lane];
    float4 o4;
    o4.x = (v.x - mean)*r*g4.x + b4.x;
    o4.y = (v.y - mean)*r*g4.y + b4.y;
    o4.z = (v.z - mean)*r*g4.z + b4.z;
    o4.w = (v.w - mean)*r*g4.w + b4.w;
    ((float4*)(g_xn2 + (size_t)warp * CH))[lane] = o4;
}

// ---------------- relative position bias ----------------
__global__ void bias_kernel(const float* __restrict__ table)
{
    int q = blockIdx.x, k = threadIdx.x;
    int qd = q >> 4, qh = (q >> 2) & 3, qw = q & 3;
    int kd = k >> 4, kh = (k >> 2) & 3, kw = k & 3;
    int idx = (qh - kh + 3) * 49 + (qd - kd + 3) * 7 + (qw - kw + 3);
    #pragma unroll
    for (int h = 0; h < HEADS; h++)
        g_bias[h * 4096 + q * 64 + k] = table[idx * HEADS + h];
}

// ---------------- weight transpose: dst[N,K] = src[K,N] ----------------
__global__ void transpose_kernel(const float* __restrict__ src, float* __restrict__ dst, int K, int N)
{
    __shared__ float tile[32][33];
    int n0 = blockIdx.x * 32, k0 = blockIdx.y * 32;
    int tx = threadIdx.x, ty = threadIdx.y;
    tile[ty][tx] = src[(size_t)(k0 + ty) * N + n0 + tx];
    __syncthreads();
    dst[(size_t)(n0 + ty) * K + k0 + tx] = tile[tx][ty];
}

// ---------------- epilogues ----------------
struct QkvEpi {
    __device__ void operator()(int m, int n, float v) const {
        int sel = n >> 7, c = n & 127;
        int head = c >> 5, e = c & 31;
        int win = m >> 6, t = m & 63;
        size_t o = (((size_t)win * HEADS + head) * NTOK + t) * HD + e;
        if (sel == 0)      g_q[o] = v * 0.17677669529663687f;
        else if (sel == 1) g_k[o] = v;
        else               g_v[o] = v;
    }
};
struct ProjEpi {
    const float* x; const float* pb;
    __device__ void operator()(int m, int n, float v) const {
        int win = m >> 6, t = m & 63;
        int b = win >> 11, widx = win & 2047;
        int wd = widx >> 8, wh = (widx >> 4) & 15, ww = widx & 15;
        int td = t >> 4, th = (t >> 2) & 3, tw = t & 3;
        int d = (wd*4 + td + 2) & 31;
        int h = (wh*4 + th + 2) & 63;
        int w = (ww*4 + tw + 2) & 63;
        size_t o = (size_t)(((b*32 + d)*64 + h)*64 + w) * CH + n;
        g_x1[o] = v + pb[n] + x[o];
    }
};
struct Mlp1Epi {
    const float* b1;
    __device__ void operator()(int m, int n, float v) const {
        float u = v + b1[n];
        float z2 = 1.5957691216057308f * (u + 0.044715f * u * u * u);
        float sig = 1.0f / (1.0f + __expf(-z2));
        g_hid[(size_t)m * HID + n] = u * sig;
    }
};
struct Mlp2Epi {
    const float* b2; float* out;
    __device__ void operator()(int m, int n, float v) const {
        size_t o = (size_t)m * CH + n;
        out[o] = v + b2[n] + g_x1[o];
    }
};

// ---------------- tf32 mma.sync GEMM ----------------
// grid: (NTILES, ROWBLK) — consecutive blocks share the A tile via L2.
template<int KTOT, class Epi>
__global__ __launch_bounds__(256, 2) void gemm_mma(
    const float* __restrict__ A, const float* __restrict__ BT, Epi epi)
{
    extern __shared__ float sm[];   // 18432 floats
    const int tid = threadIdx.x;
    const int wid = tid >> 5, lane = tid & 31;
    const int row0 = blockIdx.y * 128, col0 = blockIdx.x * 128;
    const int wm0 = (wid >> 1) * 32, wn0 = (wid & 1) * 64;
    const int g = lane >> 2, tg = lane & 3;

    float acc[2][8][4];
    #pragma unroll
    for (int mt = 0; mt < 2; mt++)
        #pragma unroll
        for (int nt = 0; nt < 8; nt++)
            #pragma unroll
            for (int c = 0; c < 4; c++) acc[mt][nt][c] = 0.0f;

    float4 ra[4], rb[4];
    auto loadG = [&](int kc) {
        const float* pA = A + (size_t)row0 * KTOT + kc * 32;
        const float* pB = BT + (size_t)col0 * KTOT + kc * 32;
        #pragma unroll
        for (int i = 0; i < 4; i++) {
            int idx = tid + i * 256;
            int r = idx >> 3, c = (idx & 7) * 4;
            ra[i] = *(const float4*)(pA + (size_t)r * KTOT + c);
            rb[i] = *(const float4*)(pB + (size_t)r * KTOT + c);
        }
    };
    auto storeS = [&](int buf) {
        float* As_ = sm + buf * 9216;
        float* Bs_ = As_ + 4608;
        #pragma unroll
        for (int i = 0; i < 4; i++) {
            int idx = tid + i * 256;
            int r = idx >> 3, c = (idx & 7) * 4;
            *(float4*)(As_ + r * 36 + c) = cvt4(ra[i]);
            *(float4*)(Bs_ + r * 36 + c) = cvt4(rb[i]);
        }
    };
    auto compute = [&](int buf) {
        const float* As_ = sm + buf * 9216;
        const float* Bs_ = As_ + 4608;
        #pragma unroll
        for (int ks = 0; ks < 4; ks++) {
            const int kk = ks * 8;
            uint32_t a[2][4], b[8][2];
            #pragma unroll
            for (int mt = 0; mt < 2; mt++) {
                int r = wm0 + mt * 16;
                a[mt][0] = __float_as_uint(As_[(r + g    ) * 36 + kk + tg    ]);
                a[mt][1] = __float_as_uint(As_[(r + g + 8) * 36 + kk + tg    ]);
                a[mt][2] = __float_as_uint(As_[(r + g    ) * 36 + kk + tg + 4]);
                a[mt][3] = __float_as_uint(As_[(r + g + 8) * 36 + kk + tg + 4]);
            }
            #pragma unroll
            for (int nt = 0; nt < 8; nt++) {
                int n = wn0 + nt * 8 + g;
                b[nt][0] = __float_as_uint(Bs_[n * 36 + kk + tg    ]);
                b[nt][1] = __float_as_uint(Bs_[n * 36 + kk + tg + 4]);
            }
            #pragma unroll
            for (int mt = 0; mt < 2; mt++)
                #pragma unroll
                for (int nt = 0; nt < 8; nt++)
                    MMA_TF32(acc[mt][nt], a[mt], b[nt]);
        }
    };

    constexpr int NKC = KTOT / 32;
    loadG(0);
    storeS(0);
    __syncthreads();
    #pragma unroll
    for (int kc = 0; kc < NKC; kc++) {
        if (kc + 1 < NKC) loadG(kc + 1);
        compute(kc & 1);
        __syncthreads();
        if (kc + 1 < NKC) {
            storeS((kc + 1) & 1);
            __syncthreads();
        }
    }

    float* st = sm;   // 128 x 132
    #pragma unroll
    for (int mt = 0; mt < 2; mt++)
        #pragma unroll
        for (int nt = 0; nt < 8; nt++) {
            int r = wm0 + mt * 16;
            int c = wn0 + nt * 8 + tg * 2;
            *(float2*)(st + (r + g    ) * 132 + c) = make_float2(acc[mt][nt][0], acc[mt][nt][1]);
            *(float2*)(st + (r + g + 8) * 132 + c) = make_float2(acc[mt][nt][2], acc[mt][nt][3]);
        }
    __syncthreads();
    #pragma unroll
    for (int i = 0; i < 64; i++) {
        int idx = tid + i * 256;
        int m = idx >> 7, n = idx & 127;
        epi(row0 + m, col0 + n, st[m * 132 + n]);
    }
}

// ---------------- attention (tensor core): one block per window ----------------
// 256 threads = 8 warps; warp w: head = w/2, query rows r0 = (w&1)*32.
// QK^T and PV via mma.sync tf32; softmax in fragments; P via register shuffles.
__global__ __launch_bounds__(256) void attn_mma_kernel(const float* __restrict__ mask)
{
    extern __shared__ float s[];
    float* Qs = s;             // [4][64][32] xor-swizzled
    float* Ks = s + 8192;      // [4][64][32]
    float* Vt = s + 16384;     // [4][32][64] (dim-major, token swizzled)
    float* Ms = s + 24576;     // [64][64] swizzled

    const int win = blockIdx.x;
    const int tid = threadIdx.x;
    const int wid = tid >> 5, lane = tid & 31;
    const int head = wid >> 1;
    const int r0 = (wid & 1) * 32;
    const int g = lane >> 2, tg = lane & 3;

    // ---- fill smem (coalesced float4 from global) ----
    const float4* bq = (const float4*)(g_q + (size_t)win * 8192);
    const float4* bk = (const float4*)(g_k + (size_t)win * 8192);
    const float4* bv = (const float4*)(g_v + (size_t)win * 8192);
    #pragma unroll
    for (int i = 0; i < 8; i++) {
        int f = tid + i * 256;        // 0..2047
        int h = f >> 9;
        int tok = (f >> 3) & 63;
        int q4 = (f & 7) * 4;
        int sw = (tok & 7) << 2;
        *(float4*)(Qs + h*2048 + tok*32 + (q4 ^ sw)) = cvt4(bq[f]);
        *(float4*)(Ks + h*2048 + tok*32 + (q4 ^ sw)) = cvt4(bk[f]);
        float4 vv = cvt4(bv[f]);
        float va[4] = {vv.x, vv.y, vv.z, vv.w};
        #pragma unroll
        for (int j = 0; j < 4; j++) {
            int d = q4 + j;
            Vt[h*2048 + d*64 + (tok ^ ((d & 7) << 2))] = va[j];
        }
    }
    const float4* mrow = (const float4*)(mask + (size_t)(win & 2047) * 4096);
    #pragma unroll
    for (int i = 0; i < 4; i++) {
        int f = tid + i * 256;        // 0..1023
        int r = f >> 4, c4 = (f & 15) * 4;
        *(float4*)(Ms + r*64 + (c4 ^ ((r & 7) << 2))) = mrow[f];
    }
    __syncthreads();

    const float* Qh = Qs + head * 2048;
    const float* Kh = Ks + head * 2048;
    const float* Vh = Vt + head * 2048;

    // ---- scores: S[32x64] = Q[32x32] @ K^T ----
    float sc[2][8][4];
    #pragma unroll
    for (int mt = 0; mt < 2; mt++)
        #pragma unroll
        for (int nt = 0; nt < 8; nt++)
            #pragma unroll
            for (int c = 0; c < 4; c++) sc[mt][nt][c] = 0.0f;

    #pragma unroll
    for (int ks = 0; ks < 4; ks++) {
        const int kk = ks * 8;
        uint32_t a[2][4], b[8][2];
        #pragma unroll
        for (int mt = 0; mt < 2; mt++) {
            int ra_ = r0 + mt*16 + g, rb_ = ra_ + 8;
            a[mt][0] = __float_as_uint(Qh[ra_*32 + ((kk+tg  ) ^ ((ra_&7)<<2))]);
            a[mt][1] = __float_as_uint(Qh[rb_*32 + ((kk+tg  ) ^ ((rb_&7)<<2))]);
            a[mt][2] = __float_as_uint(Qh[ra_*32 + ((kk+tg+4) ^ ((ra_&7)<<2))]);
            a[mt][3] = __float_as_uint(Qh[rb_*32 + ((kk+tg+4) ^ ((rb_&7)<<2))]);
        }
        #pragma unroll
        for (int nt = 0; nt < 8; nt++) {
            int n = nt*8 + g;
            b[nt][0] = __float_as_uint(Kh[n*32 + ((kk+tg  ) ^ ((n&7)<<2))]);
            b[nt][1] = __float_as_uint(Kh[n*32 + ((kk+tg+4) ^ ((n&7)<<2))]);
        }
        #pragma unroll
        for (int mt = 0; mt < 2; mt++)
            #pragma unroll
            for (int nt = 0; nt < 8; nt++)
                MMA_TF32(sc[mt][nt], a[mt], b[nt]);
    }

    // ---- bias + mask + exp + row sums ----
    const float* brow = g_bias + head * 4096;
    float rs[2][2] = {{0.f, 0.f}, {0.f, 0.f}};
    #pragma unroll
    for (int mt = 0; mt < 2; mt++) {
        int ra_ = r0 + mt*16 + g, rb_ = ra_ + 8;
        #pragma unroll
        for (int nt = 0; nt < 8; nt++) {
            int c0 = nt*8 + 2*tg;
            float2 ba = *(const float2*)(brow + ra_*64 + c0);
            float2 bb = *(const float2*)(brow + rb_*64 + c0);
            float2 ma = *(const float2*)(Ms + ra_*64 + (c0 ^ ((ra_&7)<<2)));
            float2 mb = *(const float2*)(Ms + rb_*64 + (c0 ^ ((rb_&7)<<2)));
            float e0 = __expf(sc[mt][nt][0] + ba.x + ma.x);
            float e1 = __expf(sc[mt][nt][1] + ba.y + ma.y);
            float e2 = __expf(sc[mt][nt][2] + bb.x + mb.x);
            float e3 = __expf(sc[mt][nt][3] + bb.y + mb.y);
            rs[mt][0] += e0 + e1;
            rs[mt][1] += e2 + e3;
            sc[mt][nt][0] = __uint_as_float(f2tf32(e0));
            sc[mt][nt][1] = __uint_as_float(f2tf32(e1));
            sc[mt][nt][2] = __uint_as_float(f2tf32(e2));
            sc[mt][nt][3] = __uint_as_float(f2tf32(e3));
        }
    }
    float inv[2][2];
    #pragma unroll
    for (int mt = 0; mt < 2; mt++) {
        #pragma unroll
        for (int hh = 0; hh < 2; hh++) {
            float v = rs[mt][hh];
            v += __shfl_xor_sync(0xffffffffu, v, 1);
            v += __shfl_xor_sync(0xffffffffu, v, 2);
            inv[mt][hh] = 1.0f / v;
        }
    }

    // ---- O[32x32] = P @ V ----
    float oa[2][4][4];
    #pragma unroll
    for (int mt = 0; mt < 2; mt++)
        #pragma unroll
        for (int nt = 0; nt < 4; nt++)
            #pragma unroll
            for (int c = 0; c < 4; c++) oa[mt][nt][c] = 0.0f;

    const int src0 = (lane & ~3) | (tg >> 1);
    const int src2 = (lane & ~3) | (2 + (tg >> 1));
    const bool odd = (tg & 1);
    #pragma unroll
    for (int ks = 0; ks < 8; ks++) {
        uint32_t pa[2][4];
        #pragma unroll
        for (int mt = 0; mt < 2; mt++) {
            float c0 = sc[mt][ks][0], c1 = sc[mt][ks][1];
            float c2 = sc[mt][ks][2], c3 = sc[mt][ks][3];
            float v00 = __shfl_sync(0xffffffffu, c0, src0);
            float v01 = __shfl_sync(0xffffffffu, c1, src0);
            float v10 = __shfl_sync(0xffffffffu, c2, src0);
            float v11 = __shfl_sync(0xffffffffu, c3, src0);
            float v20 = __shfl_sync(0xffffffffu, c0, src2);
            float v21 = __shfl_sync(0xffffffffu, c1, src2);
            float v30 = __shfl_sync(0xffffffffu, c2, src2);
            float v31 = __shfl_sync(0xffffffffu, c3, src2);
            pa[mt][0] = __float_as_uint(odd ? v01 : v00);
            pa[mt][1] = __float_as_uint(odd ? v11 : v10);
            pa[mt][2] = __float_as_uint(odd ? v21 : v20);
            pa[mt][3] = __float_as_uint(odd ? v31 : v30);
        }
        uint32_t vb[4][2];
        #pragma unroll
        for (int nt = 0; nt < 4; nt++) {
            int n = nt*8 + g;   // output dim
            vb[nt][0] = __float_as_uint(Vh[n*64 + ((ks*8+tg  ) ^ ((n&7)<<2))]);
            vb[nt][1] = __float_as_uint(Vh[n*64 + ((ks*8+tg+4) ^ ((n&7)<<2))]);
        }
        #pragma unroll
        for (int mt = 0; mt < 2; mt++)
            #pragma unroll
            for (int nt = 0; nt < 4; nt++)
                MMA_TF32(oa[mt][nt], pa[mt], vb[nt]);
    }

    // ---- normalize + store ----
    #pragma unroll
    for (int mt = 0; mt < 2; mt++) {
        int ra_ = r0 + mt*16 + g;
        #pragma unroll
        for (int nt = 0; nt < 4; nt++) {
            int c0 = head*32 + nt*8 + 2*tg;
            float* orow = g_attn + ((size_t)win*64 + ra_)*128 + c0;
            *(float2*)orow = make_float2(oa[mt][nt][0]*inv[mt][0], oa[mt][nt][1]*inv[mt][0]);
            *(float2*)(orow + 8*128) = make_float2(oa[mt][nt][2]*inv[mt][1], oa[mt][nt][3]*inv[mt][1]);
        }
    }
}

// ---------------- launcher ----------------
extern "C" void kernel_launch(void* const* d_in, const int* in_sizes, int n_in,
                              void* d_out, int out_size)
{
    const float* x       = (const float*)d_in[0];
    const float* mask    = (const float*)d_in[1];
    const float* n1s     = (const float*)d_in[2];
    const float* n1b     = (const float*)d_in[3];
    const float* qkv_w   = (const float*)d_in[4];
    const float* table   = (const float*)d_in[5];
    const float* proj_w  = (const float*)d_in[6];
    const float* proj_b  = (const float*)d_in[7];
    const float* n2s     = (const float*)d_in[8];
    const float* n2b     = (const float*)d_in[9];
    const float* mlp_w1  = (const float*)d_in[10];
    const float* mlp_b1  = (const float*)d_in[11];
    const float* mlp_w2  = (const float*)d_in[12];
    const float* mlp_b2  = (const float*)d_in[13];
    float* out = (float*)d_out;

    float *p_xw, *p_xn2, *p_hid, *p_attn;
    float *p_wqkv_t, *p_wproj_t, *p_w1_t, *p_w2_t;
    cudaGetSymbolAddress((void**)&p_xw,     g_xw);
    cudaGetSymbolAddress((void**)&p_xn2,    g_xn2);
    cudaGetSymbolAddress((void**)&p_hid,    g_hid);
    cudaGetSymbolAddress((void**)&p_attn,   g_attn);
    cudaGetSymbolAddress((void**)&p_wqkv_t, g_wqkv_t);
    cudaGetSymbolAddress((void**)&p_wproj_t,g_wproj_t);
    cudaGetSymbolAddress((void**)&p_w1_t,   g_w1_t);
    cudaGetSymbolAddress((void**)&p_w2_t,   g_w2_t);

    const int DSM = 73728;
    cudaFuncSetAttribute(gemm_mma<128, QkvEpi>,  cudaFuncAttributeMaxDynamicSharedMemorySize, DSM);
    cudaFuncSetAttribute(gemm_mma<128, ProjEpi>, cudaFuncAttributeMaxDynamicSharedMemorySize, DSM);
    cudaFuncSetAttribute(gemm_mma<128, Mlp1Epi>, cudaFuncAttributeMaxDynamicSharedMemorySize, DSM);
    cudaFuncSetAttribute(gemm_mma<512, Mlp2Epi>, cudaFuncAttributeMaxDynamicSharedMemorySize, DSM);
    const int ADSM = 28672 * 4;   // 112 KB
    cudaFuncSetAttribute(attn_mma_kernel, cudaFuncAttributeMaxDynamicSharedMemorySize, ADSM);

    const int ROWBLK = (int)(MROWS / 128);  // 2048

    transpose_kernel<<<dim3(12, 4),  dim3(32, 32)>>>(qkv_w,  p_wqkv_t, 128, 384);
    transpose_kernel<<<dim3(4, 4),   dim3(32, 32)>>>(proj_w, p_wproj_t, 128, 128);
    transpose_kernel<<<dim3(16, 4),  dim3(32, 32)>>>(mlp_w1, p_w1_t,   128, 512);
    transpose_kernel<<<dim3(4, 16),  dim3(32, 32)>>>(mlp_w2, p_w2_t,   512, 128);

    // 1. LN1 + shift + window partition
    ln1_shift_kernel<<<(int)(MROWS / 8), 256>>>(x, n1s, n1b);
    // 2. relative position bias
    bias_kernel<<<64, 64>>>(table);
    // 3. QKV projection (q pre-scaled); grid x = N-tile so A tile is L2-shared
    gemm_mma<128, QkvEpi><<<dim3(3, ROWBLK), 256, DSM>>>(p_xw, p_wqkv_t, QkvEpi{});
    // 4. windowed attention (tensor core)
    attn_mma_kernel<<<NWIN, 256, ADSM>>>(mask);
    // 5. output projection + window reverse + roll + residual
    gemm_mma<128, ProjEpi><<<dim3(1, ROWBLK), 256, DSM>>>(p_attn, p_wproj_t, ProjEpi{x, proj_b});
    // 6. LN2
    ln2_kernel<<<(int)(MROWS / 8), 256>>>(n2s, n2b);
    // 7. MLP up + GELU
    gemm_mma<128, Mlp1Epi><<<dim3(4, ROWBLK), 256, DSM>>>(p_xn2, p_w1_t, Mlp1Epi{mlp_b1});
    // 8. MLP down + residual -> out
    gemm_mma<512, Mlp2Epi><<<dim3(1, ROWBLK), 256, DSM>>>(p_hid, p_w2_t, Mlp2Epi{mlp_b2, out});
}